// round 2
// baseline (speedup 1.0000x reference)
#include <cuda_runtime.h>
#include <cuda_fp16.h>
#include <cstdint>

#define NB 4
#define NS 512
#define ND 768
#define NL 64

// Scratch for the rank-1 terms (bias folded into g_t2h).
__device__ float g_t2h[NB * NL * NS];
__device__ float g_t2d[NB * NL * NS];

__device__ __forceinline__ unsigned pack2(float a, float b) {
    __half2 h = __floats2half2_rn(a, b);
    return *reinterpret_cast<unsigned*>(&h);
}

// ---------------------------------------------------------------------------
// Kernel 1: t2_h[b,l,i] = head[b,i,:]·Wh[l,:] (+ bias[l]),
//           t2_d[b,l,o] = dep[b,o,:]·Wd[l,:]
// grid (S/32, B, 2), 256 threads. Tiny (0.4 GFLOP), keep simple.
// ---------------------------------------------------------------------------
__global__ void t2_kernel(const float* __restrict__ head,
                          const float* __restrict__ dep,
                          const float* __restrict__ W,
                          const float* __restrict__ bias) {
    int type = blockIdx.z;                 // 0 = head/Wh, 1 = dep/Wd
    const float* X = type ? dep : head;
    float* out = type ? g_t2d : g_t2h;
    int woff = type ? ND : 0;
    int b = blockIdx.y;
    int s0 = blockIdx.x * 32;

    __shared__ float sX[32][36];
    __shared__ float sW[64][36];

    int t = threadIdx.x;
    int row = t >> 3, c4 = (t & 7) * 4;    // smem fill mapping
    int ty = t >> 4, tx = t & 15;          // compute mapping
    float acc[2][4] = {};

    for (int k0 = 0; k0 < ND; k0 += 32) {
        *(float4*)&sX[row][c4] =
            *(const float4*)&X[(size_t)(b * NS + s0 + row) * ND + k0 + c4];
        *(float4*)&sW[row][c4] =
            *(const float4*)&W[(size_t)row * (2 * ND) + woff + k0 + c4];
        *(float4*)&sW[row + 32][c4] =
            *(const float4*)&W[(size_t)(row + 32) * (2 * ND) + woff + k0 + c4];
        __syncthreads();
#pragma unroll
        for (int kk = 0; kk < 32; kk++) {
            float x0 = sX[ty * 2 + 0][kk];
            float x1 = sX[ty * 2 + 1][kk];
#pragma unroll
            for (int j = 0; j < 4; j++) {
                float w = sW[tx + 16 * j][kk];
                acc[0][j] += x0 * w;
                acc[1][j] += x1 * w;
            }
        }
        __syncthreads();
    }
#pragma unroll
    for (int rr = 0; rr < 2; rr++) {
        int s = s0 + ty * 2 + rr;
#pragma unroll
        for (int j = 0; j < 4; j++) {
            int l = tx + 16 * j;
            float v = acc[rr][j];
            if (type == 0) v += bias[l];
            out[(size_t)(b * NL + l) * NS + s] = v;
        }
    }
}

// ---------------------------------------------------------------------------
// Kernel 2: per (b,l): out_tile[128 i x 128 o] = (head[b]*U[l]) @ dep[b]^T
//           + t2_h (broadcast over o) + t2_d (broadcast over i)   [bias in t2_h]
// fp16 operands, fp32 accumulate via mma.sync m16n8k16.
// grid (16, 64, 4), 256 threads (8 warps as 4m x 2n, each warp 32x64).
// smem: double-buffered 128x32 fp16 tiles, pitch 40 halves (conflict-free).
// ---------------------------------------------------------------------------
__global__ void __launch_bounds__(256) biaffine_main(
    const float* __restrict__ head, const float* __restrict__ dep,
    const float* __restrict__ U, float* __restrict__ out) {

    int l = blockIdx.y, b = blockIdx.z;
    int i0 = (blockIdx.x >> 2) * 128;
    int o0 = (blockIdx.x & 3) * 128;

    __shared__ __align__(16) __half sA[2][128][40];
    __shared__ __align__(16) __half sB[2][128][40];

    int t = threadIdx.x;
    int lane = t & 31, wid = t >> 5;
    int wm = wid & 3, wn = wid >> 2;
    int rbase = wm * 32, cbase = wn * 64;

    // Loader mapping: 4 threads per row, 8 halves per thread, rows t/4 and t/4+64
    int rowA = t >> 2;
    int c8 = (t & 3) * 8;
    const float* hp0 = head + ((size_t)b * NS + i0 + rowA) * ND + c8;
    const float* hp1 = hp0 + (size_t)64 * ND;
    const float* dp0 = dep + ((size_t)b * NS + o0 + rowA) * ND + c8;
    const float* dp1 = dp0 + (size_t)64 * ND;
    const float* up  = U + (size_t)l * ND + c8;

    float4 h0, h1, h2, h3, d0, d1, d2, d3, u0, u1;
    float acc[2][8][4];
#pragma unroll
    for (int mi = 0; mi < 2; mi++)
#pragma unroll
        for (int ni = 0; ni < 8; ni++)
#pragma unroll
            for (int k = 0; k < 4; k++) acc[mi][ni][k] = 0.0f;

    auto gload = [&](int k0) {
        u0 = *(const float4*)(up + k0);
        u1 = *(const float4*)(up + k0 + 4);
        h0 = *(const float4*)(hp0 + k0);
        h1 = *(const float4*)(hp0 + k0 + 4);
        h2 = *(const float4*)(hp1 + k0);
        h3 = *(const float4*)(hp1 + k0 + 4);
        d0 = *(const float4*)(dp0 + k0);
        d1 = *(const float4*)(dp0 + k0 + 4);
        d2 = *(const float4*)(dp1 + k0);
        d3 = *(const float4*)(dp1 + k0 + 4);
    };
    auto sstore = [&](int buf) {
        *(uint4*)&sA[buf][rowA][c8] = make_uint4(
            pack2(h0.x * u0.x, h0.y * u0.y), pack2(h0.z * u0.z, h0.w * u0.w),
            pack2(h1.x * u1.x, h1.y * u1.y), pack2(h1.z * u1.z, h1.w * u1.w));
        *(uint4*)&sA[buf][rowA + 64][c8] = make_uint4(
            pack2(h2.x * u0.x, h2.y * u0.y), pack2(h2.z * u0.z, h2.w * u0.w),
            pack2(h3.x * u1.x, h3.y * u1.y), pack2(h3.z * u1.z, h3.w * u1.w));
        *(uint4*)&sB[buf][rowA][c8] = make_uint4(
            pack2(d0.x, d0.y), pack2(d0.z, d0.w),
            pack2(d1.x, d1.y), pack2(d1.z, d1.w));
        *(uint4*)&sB[buf][rowA + 64][c8] = make_uint4(
            pack2(d2.x, d2.y), pack2(d2.z, d2.w),
            pack2(d3.x, d3.y), pack2(d3.z, d3.w));
    };

    gload(0);
    sstore(0);
    __syncthreads();

    const int NCH = ND / 32;  // 24
    for (int ch = 0; ch < NCH; ch++) {
        int buf = ch & 1;
        if (ch < NCH - 1) gload((ch + 1) * 32);  // global loads overlap compute

#pragma unroll
        for (int ks = 0; ks < 2; ks++) {
            int kb = ks * 16;
            unsigned af[2][4], bf[8][2];
#pragma unroll
            for (int mi = 0; mi < 2; mi++) {
                int ar = rbase + mi * 16 + (lane >> 2);
                int ac = kb + (lane & 3) * 2;
                af[mi][0] = *(const unsigned*)&sA[buf][ar][ac];
                af[mi][1] = *(const unsigned*)&sA[buf][ar + 8][ac];
                af[mi][2] = *(const unsigned*)&sA[buf][ar][ac + 8];
                af[mi][3] = *(const unsigned*)&sA[buf][ar + 8][ac + 8];
            }
#pragma unroll
            for (int ni = 0; ni < 8; ni++) {
                int bc = cbase + ni * 8 + (lane >> 2);
                int kc = kb + (lane & 3) * 2;
                bf[ni][0] = *(const unsigned*)&sB[buf][bc][kc];
                bf[ni][1] = *(const unsigned*)&sB[buf][bc][kc + 8];
            }
#pragma unroll
            for (int mi = 0; mi < 2; mi++)
#pragma unroll
                for (int ni = 0; ni < 8; ni++) {
                    asm volatile(
                        "mma.sync.aligned.m16n8k16.row.col.f32.f16.f16.f32 "
                        "{%0,%1,%2,%3}, {%4,%5,%6,%7}, {%8,%9}, {%0,%1,%2,%3};"
                        : "+f"(acc[mi][ni][0]), "+f"(acc[mi][ni][1]),
                          "+f"(acc[mi][ni][2]), "+f"(acc[mi][ni][3])
                        : "r"(af[mi][0]), "r"(af[mi][1]), "r"(af[mi][2]),
                          "r"(af[mi][3]), "r"(bf[ni][0]), "r"(bf[ni][1]));
                }
        }
        if (ch < NCH - 1) sstore(1 - buf);
        __syncthreads();
    }

    // Epilogue: fuse t2_h (+bias) and t2_d, write 256MB coalesced-ish float2s.
    size_t obase = (((size_t)(b * NL + l)) * NS + i0) * NS + o0;
    int tb = (b * NL + l) * NS;
#pragma unroll
    for (int mi = 0; mi < 2; mi++) {
        int r = rbase + mi * 16 + (lane >> 2);
        float th0 = g_t2h[tb + i0 + r];
        float th1 = g_t2h[tb + i0 + r + 8];
#pragma unroll
        for (int ni = 0; ni < 8; ni++) {
            int c = cbase + ni * 8 + (lane & 3) * 2;
            float td0 = g_t2d[tb + o0 + c];
            float td1 = g_t2d[tb + o0 + c + 1];
            float2 v0 = make_float2(acc[mi][ni][0] + th0 + td0,
                                    acc[mi][ni][1] + th0 + td1);
            float2 v1 = make_float2(acc[mi][ni][2] + th1 + td0,
                                    acc[mi][ni][3] + th1 + td1);
            *(float2*)(out + obase + (size_t)r * NS + c) = v0;
            *(float2*)(out + obase + (size_t)(r + 8) * NS + c) = v1;
        }
    }
}

extern "C" void kernel_launch(void* const* d_in, const int* in_sizes, int n_in,
                              void* d_out, int out_size) {
    const float* head = (const float*)d_in[0];
    const float* dep  = (const float*)d_in[1];
    const float* U    = (const float*)d_in[2];
    const float* W    = (const float*)d_in[3];
    const float* bias = (const float*)d_in[4];
    float* out = (float*)d_out;

    t2_kernel<<<dim3(NS / 32, NB, 2), 256>>>(head, dep, W, bias);
    biaffine_main<<<dim3(16, NL, NB), 256>>>(head, dep, U, out);
}

// round 5
// speedup vs baseline: 1.4316x; 1.4316x over previous
#include <cuda_runtime.h>
#include <cuda_fp16.h>
#include <cstdint>

#define NB 4
#define NS 512
#define ND 768
#define NL 64
#define KC 32
#define NCH 24           // 768 / 32
#define STAGES 4
#define THREADS 256

// fp16 copies of inputs + rank-1 terms (bias folded into g_t2h)
__device__ float  g_t2h[NB * NL * NS];
__device__ float  g_t2d[NB * NL * NS];
__device__ __half g_head_h[(size_t)NB * NS * ND];
__device__ __half g_dep_h[(size_t)NB * NS * ND];
__device__ __half g_U_h[NL * ND];

// smem layout (dynamic): U row (768 half = 1536B) then 4 stages of
// [A 128x32 pitch40 (10240B) | B 128x32 pitch40 (10240B)]
#define SM_U     0
#define SM_TILES 1536
#define STAGE_BYTES 20480
#define SMEM_TOTAL (SM_TILES + STAGES * STAGE_BYTES)   // 83456

static __device__ __forceinline__ uint32_t s2u(const void* p) {
    uint32_t a;
    asm("{ .reg .u64 t; cvta.to.shared.u64 t, %1; cvt.u32.u64 %0, t; }"
        : "=r"(a) : "l"(p));
    return a;
}
static __device__ __forceinline__ void cpa16(uint32_t s, const void* g) {
    asm volatile("cp.async.cg.shared.global [%0], [%1], 16;" :: "r"(s), "l"(g));
}
static __device__ __forceinline__ void cpa_commit() {
    asm volatile("cp.async.commit_group;" ::: "memory");
}
static __device__ __forceinline__ void cpa_wait2() {
    asm volatile("cp.async.wait_group 2;" ::: "memory");
}
static __device__ __forceinline__ void ldsm4(uint32_t& r0, uint32_t& r1,
                                             uint32_t& r2, uint32_t& r3,
                                             uint32_t a) {
    asm volatile("ldmatrix.sync.aligned.m8n8.x4.shared.b16 {%0,%1,%2,%3}, [%4];"
                 : "=r"(r0), "=r"(r1), "=r"(r2), "=r"(r3) : "r"(a));
}
static __device__ __forceinline__ unsigned hm2(unsigned a, unsigned b) {
    __half2 x = *reinterpret_cast<__half2*>(&a);
    __half2 y = *reinterpret_cast<__half2*>(&b);
    __half2 r = __hmul2(x, y);
    return *reinterpret_cast<unsigned*>(&r);
}

// ---------------------------------------------------------------------------
__global__ void convert_kernel(const float* __restrict__ head,
                               const float* __restrict__ dep,
                               const float* __restrict__ U) {
    size_t n = (size_t)NB * NS * ND;
    size_t stride = (size_t)gridDim.x * blockDim.x;
    for (size_t i = blockIdx.x * (size_t)blockDim.x + threadIdx.x; i < n; i += stride) {
        g_head_h[i] = __float2half_rn(head[i]);
        g_dep_h[i]  = __float2half_rn(dep[i]);
    }
    for (size_t i = blockIdx.x * (size_t)blockDim.x + threadIdx.x; i < (size_t)NL * ND;
         i += stride)
        g_U_h[i] = __float2half_rn(U[i]);
}

// ---------------------------------------------------------------------------
__global__ void t2_kernel(const float* __restrict__ head,
                          const float* __restrict__ dep,
                          const float* __restrict__ W,
                          const float* __restrict__ bias) {
    int type = blockIdx.z;
    const float* X = type ? dep : head;
    float* out = type ? g_t2d : g_t2h;
    int woff = type ? ND : 0;
    int b = blockIdx.y;
    int s0 = blockIdx.x * 32;

    __shared__ float sX[32][36];
    __shared__ float sW[64][36];

    int t = threadIdx.x;
    int row = t >> 3, c4 = (t & 7) * 4;
    int ty = t >> 4, tx = t & 15;
    float acc[2][4] = {};

    for (int k0 = 0; k0 < ND; k0 += 32) {
        *(float4*)&sX[row][c4] =
            *(const float4*)&X[(size_t)(b * NS + s0 + row) * ND + k0 + c4];
        *(float4*)&sW[row][c4] =
            *(const float4*)&W[(size_t)row * (2 * ND) + woff + k0 + c4];
        *(float4*)&sW[row + 32][c4] =
            *(const float4*)&W[(size_t)(row + 32) * (2 * ND) + woff + k0 + c4];
        __syncthreads();
#pragma unroll
        for (int kk = 0; kk < 32; kk++) {
            float x0 = sX[ty * 2 + 0][kk];
            float x1 = sX[ty * 2 + 1][kk];
#pragma unroll
            for (int j = 0; j < 4; j++) {
                float w = sW[tx + 16 * j][kk];
                acc[0][j] += x0 * w;
                acc[1][j] += x1 * w;
            }
        }
        __syncthreads();
    }
#pragma unroll
    for (int rr = 0; rr < 2; rr++) {
        int s = s0 + ty * 2 + rr;
#pragma unroll
        for (int j = 0; j < 4; j++) {
            int l = tx + 16 * j;
            float v = acc[rr][j];
            if (type == 0) v += bias[l];
            out[(size_t)(b * NL + l) * NS + s] = v;
        }
    }
}

// ---------------------------------------------------------------------------
// Main: per (b,l): out[128 i x 128 o] = (head*U[l]) @ dep^T + t2 terms.
// cp.async 4-stage pipeline, ldmatrix fragments, U applied on A fragments.
// 256 threads, 8 warps (4m x 2n), warp tile 32x64. 2 CTAs/SM.
// ---------------------------------------------------------------------------
__global__ void __launch_bounds__(THREADS, 2) biaffine_main(float* __restrict__ out) {
    extern __shared__ char smem[];
    const uint32_t su = s2u(smem);
    __half* sU = (__half*)(smem + SM_U);

    const int tid = threadIdx.x;
    const int lane = tid & 31;
    const int wid = tid >> 5;
    const int rbase = (wid & 3) * 32;
    const int cbase = (wid >> 2) * 64;

    const int l  = blockIdx.y;
    const int b  = blockIdx.z;
    const int i0 = (blockIdx.x >> 2) * 128;
    const int o0 = (blockIdx.x & 3) * 128;

    // fill mapping: 2 threads per row; thread covers 16 contiguous halves
    // (two 16B cp.async at +0 and +16 bytes)
    const int frow = tid >> 1;
    const int fh = (tid & 1) * 16;          // starting half within the row chunk
    const __half* gA = g_head_h + ((size_t)(b * NS + i0 + frow)) * ND + fh;
    const __half* gB = g_dep_h + ((size_t)(b * NS + o0 + frow)) * ND + fh;
    const uint32_t sfA = su + SM_TILES + (frow * 40 + fh) * 2;
    const uint32_t sfB = sfA + 10240;

    auto fill = [&](int s, int ch) {
        const int k0 = ch * KC;
        const uint32_t so = s * STAGE_BYTES;
        cpa16(sfA + so, gA + k0);
        cpa16(sfA + so + 16, gA + k0 + 8);
        cpa16(sfB + so, gB + k0);
        cpa16(sfB + so + 16, gB + k0 + 8);
    };

    // U row for this label
    {
        const uint32_t* gU = (const uint32_t*)(g_U_h + (size_t)l * ND);
        for (int j = tid; j < ND / 2; j += THREADS)
            ((uint32_t*)sU)[j] = gU[j];
    }

    // prologue: 3 stages in flight
    fill(0, 0); cpa_commit();
    fill(1, 1); cpa_commit();
    fill(2, 2); cpa_commit();

    float acc[2][8][4];
#pragma unroll
    for (int mi = 0; mi < 2; mi++)
#pragma unroll
        for (int ni = 0; ni < 8; ni++)
#pragma unroll
            for (int k = 0; k < 4; k++) acc[mi][ni][k] = 0.0f;

    // ldmatrix lane addressing (within a 128x32 pitch-40 tile)
    const int lrow = (lane & 7) + ((lane >> 3) & 1) * 8;  // row within 16-row group
    const int lcol = (lane >> 4) * 8;                     // 0 or 8 (k halves)

    for (int ch = 0; ch < NCH; ch++) {
        const int stage = ch & (STAGES - 1);
        cpa_wait2();
        __syncthreads();
        if (ch + 3 < NCH) fill((ch + 3) & (STAGES - 1), ch + 3);
        cpa_commit();

        const uint32_t aB = su + SM_TILES + stage * STAGE_BYTES;
        const uint32_t bB = aB + 10240;

#pragma unroll
        for (int ks = 0; ks < 2; ks++) {
            const int kb = ks * 16;
            const int kg = ch * KC + kb;
            const int c0 = (lane & 3) * 2;
            unsigned ulo = *(const unsigned*)&sU[kg + c0];
            unsigned uhi = *(const unsigned*)&sU[kg + c0 + 8];

            unsigned af[2][4], bf[8][2];
#pragma unroll
            for (int mi = 0; mi < 2; mi++) {
                uint32_t a = aB + ((rbase + mi * 16 + lrow) * 40 + kb + lcol) * 2;
                ldsm4(af[mi][0], af[mi][1], af[mi][2], af[mi][3], a);
                af[mi][0] = hm2(af[mi][0], ulo);
                af[mi][1] = hm2(af[mi][1], ulo);
                af[mi][2] = hm2(af[mi][2], uhi);
                af[mi][3] = hm2(af[mi][3], uhi);
            }
#pragma unroll
            for (int g = 0; g < 4; g++) {
                uint32_t a = bB + ((cbase + g * 16 + lrow) * 40 + kb + lcol) * 2;
                ldsm4(bf[2 * g][0], bf[2 * g + 1][0], bf[2 * g][1], bf[2 * g + 1][1], a);
            }
#pragma unroll
            for (int mi = 0; mi < 2; mi++)
#pragma unroll
                for (int ni = 0; ni < 8; ni++) {
                    asm volatile(
                        "mma.sync.aligned.m16n8k16.row.col.f32.f16.f16.f32 "
                        "{%0,%1,%2,%3}, {%4,%5,%6,%7}, {%8,%9}, {%0,%1,%2,%3};"
                        : "+f"(acc[mi][ni][0]), "+f"(acc[mi][ni][1]),
                          "+f"(acc[mi][ni][2]), "+f"(acc[mi][ni][3])
                        : "r"(af[mi][0]), "r"(af[mi][1]), "r"(af[mi][2]),
                          "r"(af[mi][3]), "r"(bf[ni][0]), "r"(bf[ni][1]));
                }
        }
        __syncthreads();
    }

    // Epilogue: fuse t2_h (+bias) and t2_d
    size_t obase = (((size_t)(b * NL + l)) * NS + i0) * NS + o0;
    int tb = (b * NL + l) * NS;
#pragma unroll
    for (int mi = 0; mi < 2; mi++) {
        int r = rbase + mi * 16 + (lane >> 2);
        float th0 = g_t2h[tb + i0 + r];
        float th1 = g_t2h[tb + i0 + r + 8];
#pragma unroll
        for (int ni = 0; ni < 8; ni++) {
            int c = cbase + ni * 8 + (lane & 3) * 2;
            float td0 = g_t2d[tb + o0 + c];
            float td1 = g_t2d[tb + o0 + c + 1];
            float2 v0 = make_float2(acc[mi][ni][0] + th0 + td0,
                                    acc[mi][ni][1] + th0 + td1);
            float2 v1 = make_float2(acc[mi][ni][2] + th1 + td0,
                                    acc[mi][ni][3] + th1 + td1);
            *(float2*)(out + obase + (size_t)r * NS + c) = v0;
            *(float2*)(out + obase + (size_t)(r + 8) * NS + c) = v1;
        }
    }
}

extern "C" void kernel_launch(void* const* d_in, const int* in_sizes, int n_in,
                              void* d_out, int out_size) {
    const float* head = (const float*)d_in[0];
    const float* dep  = (const float*)d_in[1];
    const float* U    = (const float*)d_in[2];
    const float* W    = (const float*)d_in[3];
    const float* bias = (const float*)d_in[4];
    float* out = (float*)d_out;

    cudaFuncSetAttribute(biaffine_main,
                         cudaFuncAttributeMaxDynamicSharedMemorySize, SMEM_TOTAL);

    convert_kernel<<<512, 256>>>(head, dep, U);
    t2_kernel<<<dim3(NS / 32, NB, 2), 256>>>(head, dep, W, bias);
    biaffine_main<<<dim3(16, NL, NB), 256, SMEM_TOTAL>>>(out);
}